// round 14
// baseline (speedup 1.0000x reference)
#include <cuda_runtime.h>
#include <cstdint>

// LengthRegulator: expand hidden_phonems [B,L,D] by durations [B,L] into
// out [B, max_T, D], zero-padded beyond totals[b].
//
// R14: SINGLE-WAVE kernel. 512 blocks (32 batches x 16), 256 thr, low regs
// -> 4 CTAs/SM -> whole grid resident at once: zero wave transitions
// (R13 proved instruction count irrelevant; remaining suspect is CTA-churn /
// wave-transition overhead of 1-4k short-lived blocks).
// Block owns 32 consecutive phonemes: ONE packed (total,prefix) reduction,
// then 8 segments of exact-unrolled switch stores with a rolling prefix.

#define B_CONST 32
#define L_CONST 512
#define D_CONST 256
#define D4 (D_CONST / 4)
#define BLOCKS_PER_BATCH 16
#define P_PER_BLK 32                      // phonemes per block
#define SEGS 8                            // 4 phonemes per segment

__global__ void __launch_bounds__(256, 4) lr_fused(
    const float4* __restrict__ hidden4,
    const int*    __restrict__ durations,
    float4*       __restrict__ out4,
    int max_T)
{
    const int t        = threadIdx.x;            // 0..255
    const int fgrp     = t >> 6;                 // [0,4): phoneme within quad
    const int lane64   = t & 63;                 // float4 lane over D
    const int lane     = t & 31;
    const int blk      = blockIdx.x;             // 0..511
    const int b        = blk >> 4;               // batch
    const int blkLocal = blk & (BLOCKS_PER_BATCH - 1);
    const int l0       = blkLocal * P_PER_BLK;   // multiple of 32

    const int* __restrict__ dbat = durations + b * L_CONST;

    // ---- packed per-warp reduction over all 512 durations:
    //      low 16 = batch total, high 16 = exclusive prefix(l0)
    unsigned packed = 0;
    #pragma unroll
    for (int p = 0; p < 4; ++p) {
        const int i = p * 128 + lane * 4;
        const int4 dd = *(const int4*)(dbat + i);
        const unsigned full = (unsigned)(dd.x + dd.y + dd.z + dd.w);
        packed += full + (((i < l0) ? full : 0u) << 16);
    }
    packed = __reduce_add_sync(0xffffffffu, packed);   // REDUX.SUM

    const int total = (int)(packed & 0xFFFFu);
    int run = (int)(packed >> 16);               // rolling exclusive prefix

    const float4* __restrict__ hbase =
        hidden4 + ((size_t)b * L_CONST + l0) * D4 + lane64;
    float4* __restrict__ obase = out4 + (size_t)b * max_T * D4 + lane64;

    // ---- 8 segments x 4 phonemes, rolling prefix
    for (int s = 0; s < SEGS; ++s) {
        const int4 q = *(const int4*)(dbat + l0 + 4 * s);   // warp-uniform L1 hit
        const int d     = (fgrp == 0) ? q.x : (fgrp == 1) ? q.y
                        : (fgrp == 2) ? q.z : q.w;
        const int local = ((fgrp > 0) ? q.x : 0) + ((fgrp > 1) ? q.y : 0)
                        + ((fgrp > 2) ? q.z : 0);

        const float4 v = __ldcs(&hbase[(4 * s + fgrp) * D4]);

        float4* dst = obase + (size_t)(run + local) * D4;
        switch (d) {
            case 7: __stcs(dst + 6 * D4, v);  // fallthrough
            case 6: __stcs(dst + 5 * D4, v);
            case 5: __stcs(dst + 4 * D4, v);
            case 4: __stcs(dst + 3 * D4, v);
            case 3: __stcs(dst + 2 * D4, v);
            case 2: __stcs(dst + 1 * D4, v);
            case 1: __stcs(dst + 0 * D4, v);
            default: break;
        }
        run += q.x + q.y + q.z + q.w;
    }

    // ---- tail zeroing: strided share of [total, max_T), stride 64 frames
    const float4 zero = make_float4(0.f, 0.f, 0.f, 0.f);
    for (int f = total + blkLocal * 4 + fgrp; f < max_T;
         f += 4 * BLOCKS_PER_BATCH) {
        __stcs(obase + (size_t)f * D4, zero);
    }
}

extern "C" void kernel_launch(void* const* d_in, const int* in_sizes, int n_in,
                              void* d_out, int out_size) {
    const float* hidden    = (const float*)d_in[0];   // [B, L, D] fp32
    const int*   durations = (const int*)d_in[1];     // [B, L] int32
    float*       out       = (float*)d_out;

    const int max_T = out_size / (B_CONST * D_CONST);

    lr_fused<<<B_CONST * BLOCKS_PER_BATCH, 256>>>(
        (const float4*)hidden, durations, (float4*)out, max_T);
}

// round 15
// speedup vs baseline: 1.0021x; 1.0021x over previous
#include <cuda_runtime.h>
#include <cstdint>

// LengthRegulator: expand hidden_phonems [B,L,D] by durations [B,L] into
// out [B, max_T, D], zero-padded beyond totals[b].
//
// R15: R12 body + MLP=2 on row loads. Each 64-lane group owns 2 phonemes
// (p and p+4): both row LDGs issued before either store burst (independent,
// latency-overlapped), one per-warp (total,prefix) reduction amortized over
// 2x stores (duration re-read traffic halved). Exact-unrolled switch store
// runs, streaming ld/st, low regs.

#define B_CONST 32
#define L_CONST 512
#define D_CONST 256
#define D4 (D_CONST / 4)
#define P_PER_BLK 8
#define BLOCKS_PER_BATCH (L_CONST / P_PER_BLK)   // 64

__global__ void __launch_bounds__(256) lr_fused(
    const float4* __restrict__ hidden4,
    const int*    __restrict__ durations,
    float4*       __restrict__ out4,
    int max_T)
{
    const int t        = threadIdx.x;            // 0..255
    const int fgrp     = t >> 6;                 // [0,4)
    const int lane64   = t & 63;                 // float4 lane over D
    const int lane     = t & 31;
    const int blk      = blockIdx.x;             // 0..2047
    const int b        = blk >> 6;               // batch
    const int blkLocal = blk & (BLOCKS_PER_BATCH - 1);
    const int l0       = blkLocal * P_PER_BLK;   // multiple of 8

    const int* __restrict__ dbat = durations + b * L_CONST;

    // ---- packed per-warp reduction over all 512 durations:
    //      low 16 = batch total, high 16 = exclusive prefix(l0)
    unsigned packed = 0;
    #pragma unroll
    for (int p = 0; p < 4; ++p) {
        const int i = p * 128 + lane * 4;
        const int4 dd = *(const int4*)(dbat + i);
        const unsigned full = (unsigned)(dd.x + dd.y + dd.z + dd.w);
        packed += full + (((i < l0) ? full : 0u) << 16);
    }
    packed = __reduce_add_sync(0xffffffffu, packed);   // REDUX.SUM

    const int total  = (int)(packed & 0xFFFFu);
    const int prefix = (int)(packed >> 16);

    // ---- my two phonemes: p0 = l0+fgrp, p1 = l0+4+fgrp (warp-uniform quads)
    const int4 qa = *(const int4*)(dbat + l0);
    const int4 qb = *(const int4*)(dbat + l0 + 4);
    const int sumA = qa.x + qa.y + qa.z + qa.w;

    const int d0 = (fgrp == 0) ? qa.x : (fgrp == 1) ? qa.y : (fgrp == 2) ? qa.z : qa.w;
    const int o0 = ((fgrp > 0) ? qa.x : 0) + ((fgrp > 1) ? qa.y : 0)
                 + ((fgrp > 2) ? qa.z : 0);
    const int d1 = (fgrp == 0) ? qb.x : (fgrp == 1) ? qb.y : (fgrp == 2) ? qb.z : qb.w;
    const int o1 = ((fgrp > 0) ? qb.x : 0) + ((fgrp > 1) ? qb.y : 0)
                 + ((fgrp > 2) ? qb.z : 0);

    const int s0 = prefix + o0;
    const int s1 = prefix + sumA + o1;

    // ---- both row loads issued back-to-back (MLP=2, latency overlapped)
    const float4* __restrict__ hbase =
        hidden4 + ((size_t)b * L_CONST + l0 + fgrp) * D4 + lane64;
    const float4 v0 = __ldcs(&hbase[0]);
    const float4 v1 = __ldcs(&hbase[4 * D4]);

    float4* __restrict__ obase = out4 + (size_t)b * max_T * D4 + lane64;

    float4* dst0 = obase + (size_t)s0 * D4;
    switch (d0) {
        case 7: __stcs(dst0 + 6 * D4, v0);  // fallthrough
        case 6: __stcs(dst0 + 5 * D4, v0);
        case 5: __stcs(dst0 + 4 * D4, v0);
        case 4: __stcs(dst0 + 3 * D4, v0);
        case 3: __stcs(dst0 + 2 * D4, v0);
        case 2: __stcs(dst0 + 1 * D4, v0);
        case 1: __stcs(dst0 + 0 * D4, v0);
        default: break;
    }
    float4* dst1 = obase + (size_t)s1 * D4;
    switch (d1) {
        case 7: __stcs(dst1 + 6 * D4, v1);  // fallthrough
        case 6: __stcs(dst1 + 5 * D4, v1);
        case 5: __stcs(dst1 + 4 * D4, v1);
        case 4: __stcs(dst1 + 3 * D4, v1);
        case 3: __stcs(dst1 + 2 * D4, v1);
        case 2: __stcs(dst1 + 1 * D4, v1);
        case 1: __stcs(dst1 + 0 * D4, v1);
        default: break;
    }

    // ---- tail zeroing: strided share of [total, max_T), stride 256 frames
    const float4 zero = make_float4(0.f, 0.f, 0.f, 0.f);
    for (int f = total + blkLocal * 4 + fgrp; f < max_T;
         f += 4 * BLOCKS_PER_BATCH) {
        __stcs(obase + (size_t)f * D4, zero);
    }
}

extern "C" void kernel_launch(void* const* d_in, const int* in_sizes, int n_in,
                              void* d_out, int out_size) {
    const float* hidden    = (const float*)d_in[0];   // [B, L, D] fp32
    const int*   durations = (const int*)d_in[1];     // [B, L] int32
    float*       out       = (float*)d_out;

    const int max_T = out_size / (B_CONST * D_CONST);

    lr_fused<<<B_CONST * BLOCKS_PER_BATCH, 256>>>(
        (const float4*)hidden, durations, (float4*)out, max_T);
}